// round 14
// baseline (speedup 1.0000x reference)
#include <cuda_runtime.h>
#include <cuda_bf16.h>
#include <math.h>
#include <stdint.h>

// Problem constants
#define Bsz 2
#define Tn 2048
#define Dm 2048
#define NHq 16
#define NKV 8
#define HD 128
#define MROWS (Bsz * Tn)          // 4096 tokens
#define QKVN 4096                 // 2048 q | 1024 k | 1024 v
#define KOFF 2048
#define VOFF 3072
#define ENCN 2048
#define K3 6144                   // 3x split-bf16 K dimension
#define BIG_NEG -2.3819763e38f

// Scratch (device globals: allocation-free per harness rules)
__device__ __nv_bfloat16 g_wb3[(size_t)K3 * QKVN];  // QKV weights, [K3][N] split-bf16
__device__ __nv_bfloat16 g_wo3[(size_t)K3 * ENCN];  // out weights, [K3][N] split-bf16
__device__ __nv_bfloat16 g_a3[(size_t)MROWS * K3];  // activations, [M][K3] split-bf16
__device__ float g_qkv[(size_t)MROWS * QKVN];       // QKV projections (pre-rope)
__device__ __nv_bfloat16 g_sh[(size_t)MROWS * QKVN];  // rope'd qkv hi plane
__device__ __nv_bfloat16 g_sl[(size_t)MROWS * QKVN];  // rope'd qkv lo plane

// ---------------------------------------------------------------------------
#define CPA16(dst, src) \
    asm volatile("cp.async.cg.shared.global [%0], [%1], 16;" ::"r"(dst), "l"(src))
#define LDSM4(r, addr)                                                        \
    asm volatile("ldmatrix.sync.aligned.m8n8.x4.shared.b16 {%0,%1,%2,%3},[%4];" \
                 : "=r"((r)[0]), "=r"((r)[1]), "=r"((r)[2]), "=r"((r)[3])     \
                 : "r"(addr))
#define LDSM4T(r, addr)                                                       \
    asm volatile(                                                             \
        "ldmatrix.sync.aligned.m8n8.x4.trans.shared.b16 {%0,%1,%2,%3},[%4];"  \
        : "=r"((r)[0]), "=r"((r)[1]), "=r"((r)[2]), "=r"((r)[3])              \
        : "r"(addr))
#define MMA_B16(d, a, b0, b1)                                                 \
    asm volatile(                                                             \
        "mma.sync.aligned.m16n8k16.row.col.f32.bf16.bf16.f32 "                \
        "{%0,%1,%2,%3},{%4,%5,%6,%7},{%8,%9},{%0,%1,%2,%3};"                  \
        : "+f"((d)[0]), "+f"((d)[1]), "+f"((d)[2]), "+f"((d)[3])              \
        : "r"((a)[0]), "r"((a)[1]), "r"((a)[2]), "r"((a)[3]), "r"(b0), "r"(b1))

__device__ __forceinline__ unsigned pack2bf(float a, float b) {
    __nv_bfloat162 h = __floats2bfloat162_rn(a, b);
    return *(unsigned*)&h;
}

// ---------------------------------------------------------------------------
// Pack w_q + w_kv into split-bf16 [K3=6144][4096]: row blocks [hi | lo | hi]
// ---------------------------------------------------------------------------
__global__ void pack_w3_kernel(const float* __restrict__ wq,
                               const float* __restrict__ wkv) {
    size_t idx = (size_t)blockIdx.x * blockDim.x + threadIdx.x;
    if (idx >= (size_t)K3 * QKVN) return;
    int j = (int)(idx & (QKVN - 1));
    int k3 = (int)(idx >> 12);
    int seg = k3 >> 11;
    int d = k3 & 2047;
    float w;
    if (j < KOFF) {
        int n = j >> 7, h = j & 127;
        w = wq[((size_t)n * Dm + d) * HD + h];
    } else if (j < VOFF) {
        int jj = j - KOFF;
        int n = jj >> 7, h = jj & 127;
        w = wkv[((size_t)n * Dm + d) * HD + h];
    } else {
        int jj = j - VOFF;
        int n = jj >> 7, h = jj & 127;
        w = wkv[((size_t)(NKV + n) * Dm + d) * HD + h];
    }
    __nv_bfloat16 hi = __float2bfloat16(w);
    g_wb3[idx] = (seg == 1) ? __float2bfloat16(w - __bfloat162float(hi)) : hi;
}

__global__ void pack_wo3_kernel(const float* __restrict__ wout) {
    size_t idx = (size_t)blockIdx.x * blockDim.x + threadIdx.x;
    if (idx >= (size_t)K3 * ENCN) return;
    int d = (int)(idx & (ENCN - 1));
    int k3 = (int)(idx >> 11);
    int seg = k3 >> 11;
    int kk = k3 & 2047;
    float w = wout[(size_t)kk * ENCN + d];
    __nv_bfloat16 hi = __float2bfloat16(w);
    g_wo3[idx] = (seg == 1) ? __float2bfloat16(w - __bfloat162float(hi)) : hi;
}

// Split fp32 [4096][2048] into g_a3 [4096][6144]: cols [hi|hi|lo]
__global__ void split3_kernel(const float* __restrict__ src) {
    size_t idx = (size_t)blockIdx.x * blockDim.x + threadIdx.x;
    if (idx >= (size_t)MROWS * 2048) return;
    int k = (int)(idx & 2047);
    int m = (int)(idx >> 11);
    float a = src[idx];
    __nv_bfloat16 hi = __float2bfloat16(a);
    __nv_bfloat16 lo = __float2bfloat16(a - __bfloat162float(hi));
    __nv_bfloat16* dst = g_a3 + (size_t)m * K3;
    dst[k] = hi;
    dst[k + 2048] = hi;
    dst[k + 4096] = lo;
}

// ---------------------------------------------------------------------------
// Fused RoPE + hi/lo split: reads g_qkv fp32, writes g_sh/g_sl bf16 planes.
// ---------------------------------------------------------------------------
__device__ __forceinline__ void put_hl(size_t off, float v) {
    __nv_bfloat16 hi = __float2bfloat16(v);
    g_sh[off] = hi;
    g_sl[off] = __float2bfloat16(v - __bfloat162float(hi));
}

__global__ void rope_split_kernel(const int* __restrict__ positions) {
    int idx = blockIdx.x * blockDim.x + threadIdx.x;
    if (idx >= MROWS * 2048) return;
    int p = idx & 2047;
    int m = idx >> 11;
    size_t rowOff = (size_t)m * QKVN;
    if (p < 1536) {
        int head = p >> 6, pp = p & 63;
        float t = (float)positions[m];
        float frac = (float)(2 * pp) * (1.0f / 128.0f);
        float timescale = powf(10000.0f, frac);
        float ang = t / timescale;
        float s, c;
        sincosf(ang, &s, &c);
        int col = ((head < NHq) ? head * HD : KOFF + (head - NHq) * HD) + pp;
        float scale = (head < NHq) ? 0.08838834764831845f : 1.0f;
        const float* base = g_qkv + rowOff + col;
        float x1 = base[0], x2 = base[64];
        put_hl(rowOff + col, (x1 * c - x2 * s) * scale);
        put_hl(rowOff + col + 64, (x2 * c + x1 * s) * scale);
    } else {
        int col = VOFF + (p - 1536) * 2;
        put_hl(rowOff + col, g_qkv[rowOff + col]);
        put_hl(rowOff + col + 1, g_qkv[rowOff + col + 1]);
    }
}

// ---------------------------------------------------------------------------
// Split-bf16 GEMM (r5-proven config): 128x128x32 tile, 4-stage cp.async
// pipeline, wait_group 2, 256 threads, 2 CTAs/SM.
// ---------------------------------------------------------------------------
#define GBM 128
#define GBK 32
#define ASTR 40
#define BSTR 136
#define NSTG 4
#define A_BY (GBM * ASTR * 2)     // 10240
#define B_BY (GBK * BSTR * 2)     // 8704
#define STG_BY (A_BY + B_BY)      // 18944

#define GEMM_ISSUE(itv)                                                       \
    {                                                                         \
        const int k0 = (itv) * GBK;                                           \
        const unsigned aOff = smBase + ((itv) % NSTG) * STG_BY;               \
        const unsigned bOff = aOff + A_BY;                                    \
        CPA16(aOff + (arow * ASTR + ach) * 2,                                 \
              A + (size_t)(rowBlock + arow) * K3 + k0 + ach);                 \
        CPA16(aOff + ((arow + 64) * ASTR + ach) * 2,                          \
              A + (size_t)(rowBlock + arow + 64) * K3 + k0 + ach);            \
        CPA16(bOff + (brow * BSTR + bch) * 2,                                 \
              B + (size_t)(k0 + brow) * N + colBlock + bch);                  \
        CPA16(bOff + ((brow + 16) * BSTR + bch) * 2,                          \
              B + (size_t)(k0 + brow + 16) * N + colBlock + bch);             \
        asm volatile("cp.async.commit_group;");                               \
    }

__global__ __launch_bounds__(256, 2) void bf3_gemm_kernel(
    const __nv_bfloat16* __restrict__ A, const __nv_bfloat16* __restrict__ B,
    float* __restrict__ C, int N) {
    extern __shared__ __align__(16) char gsm[];
    const unsigned smBase = (unsigned)__cvta_generic_to_shared(gsm);
    const int tid = threadIdx.x;
    const int lane = tid & 31, warp = tid >> 5;
    const int warpM = warp >> 1, warpN = warp & 1;
    const int rowBlock = blockIdx.y * GBM, colBlock = blockIdx.x * 128;

    const int arow = tid >> 2, ach = (tid & 3) * 8;
    const int brow = tid >> 4, bch = (tid & 15) * 8;

    const int NIT = K3 / GBK;  // 192
    GEMM_ISSUE(0);
    GEMM_ISSUE(1);
    GEMM_ISSUE(2);

    float acc[2][8][4] = {};
    const int ldRow = (lane & 7) + ((lane >> 3) & 1) * 8;
    const int ldCol = (lane >> 4) * 8;

    for (int it = 0; it < NIT; it++) {
        asm volatile("cp.async.wait_group 2;" ::: "memory");
        __syncthreads();
        if (it + NSTG - 1 < NIT) GEMM_ISSUE(it + NSTG - 1);

        const unsigned aOff = smBase + (it % NSTG) * STG_BY;
        const unsigned bOff = aOff + A_BY;
#pragma unroll
        for (int ks = 0; ks < 2; ks++) {
            unsigned af[2][4];
#pragma unroll
            for (int mt = 0; mt < 2; mt++) {
                unsigned addr =
                    aOff + ((warpM * 32 + mt * 16 + ldRow) * ASTR + ks * 16 + ldCol) * 2;
                LDSM4(af[mt], addr);
            }
            unsigned bfr[8][2];
#pragma unroll
            for (int np = 0; np < 4; np++) {
                unsigned addr =
                    bOff + ((ks * 16 + ldRow) * BSTR + warpN * 64 + np * 16 + ldCol) * 2;
                asm volatile(
                    "ldmatrix.sync.aligned.m8n8.x4.trans.shared.b16 {%0,%1,%2,%3}, [%4];"
                    : "=r"(bfr[np * 2][0]), "=r"(bfr[np * 2][1]),
                      "=r"(bfr[np * 2 + 1][0]), "=r"(bfr[np * 2 + 1][1])
                    : "r"(addr));
            }
#pragma unroll
            for (int mt = 0; mt < 2; mt++)
#pragma unroll
                for (int nt = 0; nt < 8; nt++)
                    MMA_B16(acc[mt][nt], af[mt], bfr[nt][0], bfr[nt][1]);
        }
    }

    const int gid = lane >> 2, tig = lane & 3;
#pragma unroll
    for (int mt = 0; mt < 2; mt++) {
        int r0 = rowBlock + warpM * 32 + mt * 16 + gid;
#pragma unroll
        for (int nt = 0; nt < 8; nt++) {
            int c = colBlock + warpN * 64 + nt * 8 + tig * 2;
            *(float2*)&C[(size_t)r0 * N + c] =
                make_float2(acc[mt][nt][0], acc[mt][nt][1]);
            *(float2*)&C[(size_t)(r0 + 8) * N + c] =
                make_float2(acc[mt][nt][2], acc[mt][nt][3]);
        }
    }
}

// ---------------------------------------------------------------------------
// Tensor-core flash attention v3, split-bf16 3-term, LDSM-deduped.
// CTA: 64 q-rows x 1 head x 1 batch; 128 threads (4 warps x 16 rows).
// Single-stage KV smem (Kh/Kl/Vh/Vl, 64 rows) = 69.6 KB -> 3 CTAs/SM.
// Q fragments loaded per-kc directly from global (L1-resident).
// Split K/V commit groups: K load overlaps softmax, V load overlaps S.
// ---------------------------------------------------------------------------
#define ATS 136
#define PL (64 * ATS * 2)            // one plane, bytes (17408)
#define ATTN_SMEM (4 * PL)           // 69632 bytes

__global__ __launch_bounds__(128, 3) void attn_mma_kernel() {
    extern __shared__ __align__(16) __nv_bfloat16 sm[];
    const int tid = threadIdx.x, lane = tid & 31, warp = tid >> 5;  // 4 warps
    const int tq = 31 - blockIdx.x;      // heavy tiles first
    const int n = blockIdx.y, b = blockIdx.z, kvh = n >> 1;
    const unsigned smBase = (unsigned)__cvta_generic_to_shared(sm);

    // KV cp.async mapping: plane 64 rows x 128 cols; 8 chunks per thread
    const int kvRow = tid >> 1;          // 0..63
    const int kvC = (tid & 1) * 64;      // 0 or 64
    const size_t kRowBase = (size_t)(b * Tn) * QKVN + KOFF + kvh * HD;
    const size_t vRowBase = (size_t)(b * Tn) * QKVN + VOFF + kvh * HD;

    const int gid = lane >> 2, tig = lane & 3;
    // Q fragment global base addresses (rows gid and gid+8 of this warp's 16)
    const size_t r0q = (size_t)(b * Tn + tq * 64 + warp * 16 + gid) * QKVN +
                       n * HD + tig * 2;
    const size_t r1q = r0q + 8 * QKVN;

    const int gr0 = tq * 64 + warp * 16 + gid;

    const int bkRow = ((lane >> 4) & 1) * 8 + (lane & 7);
    const int bkCol = ((lane >> 3) & 1) * 8;
    const int vRow = ((lane >> 3) & 1) * 8 + (lane & 7);
    const int vCol = ((lane >> 4) & 1) * 8;

#define ISSUE_K(ts_)                                                          \
    {                                                                         \
        size_t kr = kRowBase + (size_t)((ts_) * 64 + kvRow) * QKVN + kvC;     \
        _Pragma("unroll")                                                     \
        for (int c = 0; c < 8; c++) {                                         \
            CPA16(smBase + (kvRow * ATS + kvC + c * 8) * 2, g_sh + kr + c * 8); \
            CPA16(smBase + PL + (kvRow * ATS + kvC + c * 8) * 2,              \
                  g_sl + kr + c * 8);                                         \
        }                                                                     \
    }
#define ISSUE_V(ts_)                                                          \
    {                                                                         \
        size_t vr = vRowBase + (size_t)((ts_) * 64 + kvRow) * QKVN + kvC;     \
        _Pragma("unroll")                                                     \
        for (int c = 0; c < 8; c++) {                                         \
            CPA16(smBase + 2 * PL + (kvRow * ATS + kvC + c * 8) * 2,          \
                  g_sh + vr + c * 8);                                         \
            CPA16(smBase + 3 * PL + (kvRow * ATS + kvC + c * 8) * 2,          \
                  g_sl + vr + c * 8);                                         \
        }                                                                     \
    }

    // Prologue: K0 then V0, separate commit groups
    ISSUE_K(0);
    asm volatile("cp.async.commit_group;" ::: "memory");
    ISSUE_V(0);
    asm volatile("cp.async.commit_group;" ::: "memory");

    float oacc[16][4] = {};
    float m0 = -1e30f, m1 = -1e30f, l0 = 0.f, l1 = 0.f;

    const int nTiles = tq + 1;
    for (int ts = 0; ts < nTiles; ts++) {
        // K(ts) ready (pending <= 1 leaves only V(ts) / newer)
        asm volatile("cp.async.wait_group 1;" ::: "memory");
        __syncthreads();   // K visible; V buffer free from prev PV

        // ---- S = softcap(Q K^T), 3-term, Q frags from global (L1) --------
        float sa[8][4] = {};
#pragma unroll
        for (int kc = 0; kc < 8; kc++) {
            unsigned qh[4], ql[4];
            qh[0] = *(const unsigned*)(g_sh + r0q + kc * 16);
            qh[1] = *(const unsigned*)(g_sh + r1q + kc * 16);
            qh[2] = *(const unsigned*)(g_sh + r0q + kc * 16 + 8);
            qh[3] = *(const unsigned*)(g_sh + r1q + kc * 16 + 8);
            ql[0] = *(const unsigned*)(g_sl + r0q + kc * 16);
            ql[1] = *(const unsigned*)(g_sl + r1q + kc * 16);
            ql[2] = *(const unsigned*)(g_sl + r0q + kc * 16 + 8);
            ql[3] = *(const unsigned*)(g_sl + r1q + kc * 16 + 8);
#pragma unroll
            for (int ntp = 0; ntp < 4; ntp++) {
                unsigned bf[4];
                const unsigned boff = ((ntp * 16 + bkRow) * ATS + kc * 16 + bkCol) * 2;
                LDSM4(bf, smBase + boff);            // Kh
                MMA_B16(sa[2 * ntp], qh, bf[0], bf[1]);
                MMA_B16(sa[2 * ntp + 1], qh, bf[2], bf[3]);
                MMA_B16(sa[2 * ntp], ql, bf[0], bf[1]);
                MMA_B16(sa[2 * ntp + 1], ql, bf[2], bf[3]);
                LDSM4(bf, smBase + PL + boff);       // Kl
                MMA_B16(sa[2 * ntp], qh, bf[0], bf[1]);
                MMA_B16(sa[2 * ntp + 1], qh, bf[2], bf[3]);
            }
        }
        __syncthreads();   // all warps done reading K buffer
        if (ts + 1 < nTiles) ISSUE_K(ts + 1);
        asm volatile("cp.async.commit_group;" ::: "memory");

        // ---- softcap + causal mask + online softmax (K load in flight) ----
        const bool needMask = (ts * 64 + 63) > (tq * 64 + warp * 16);
        float tm0 = -1e30f, tm1 = -1e30f;
#pragma unroll
        for (int nt = 0; nt < 8; nt++) {
#pragma unroll
            for (int j = 0; j < 4; j++) {
                float x = fminf(fmaxf(sa[nt][j] * 0.02f, -8.f), 8.f);
                float e = __expf(2.f * x);
                float v = 50.f * __fdividef(e - 1.f, e + 1.f);
                if (needMask) {
                    int gc = ts * 64 + nt * 8 + tig * 2 + (j & 1);
                    int gr = gr0 + ((j >= 2) ? 8 : 0);
                    if (gc > gr) v = BIG_NEG;
                }
                sa[nt][j] = v;
                if (j < 2) tm0 = fmaxf(tm0, v);
                else       tm1 = fmaxf(tm1, v);
            }
        }
        tm0 = fmaxf(tm0, __shfl_xor_sync(0xffffffff, tm0, 1));
        tm0 = fmaxf(tm0, __shfl_xor_sync(0xffffffff, tm0, 2));
        tm1 = fmaxf(tm1, __shfl_xor_sync(0xffffffff, tm1, 1));
        tm1 = fmaxf(tm1, __shfl_xor_sync(0xffffffff, tm1, 2));
        float mn0 = fmaxf(m0, tm0), mn1 = fmaxf(m1, tm1);
        float sc0 = __expf(m0 - mn0), sc1 = __expf(m1 - mn1);
        m0 = mn0; m1 = mn1;
        l0 *= sc0; l1 *= sc1;
#pragma unroll
        for (int nt = 0; nt < 8; nt++) {
            float p0 = __expf(sa[nt][0] - mn0);
            float p1 = __expf(sa[nt][1] - mn0);
            float p2 = __expf(sa[nt][2] - mn1);
            float p3 = __expf(sa[nt][3] - mn1);
            sa[nt][0] = p0; sa[nt][1] = p1; sa[nt][2] = p2; sa[nt][3] = p3;
            l0 += p0 + p1; l1 += p2 + p3;
        }
#pragma unroll
        for (int nt = 0; nt < 16; nt++) {
            oacc[nt][0] *= sc0; oacc[nt][1] *= sc0;
            oacc[nt][2] *= sc1; oacc[nt][3] *= sc1;
        }

        // Pack P into A fragments (hi + lo)
        unsigned phf[4][4], plf[4][4];
#pragma unroll
        for (int kc = 0; kc < 4; kc++) {
            float c00 = sa[2 * kc][0], c01 = sa[2 * kc][1];
            float c02 = sa[2 * kc][2], c03 = sa[2 * kc][3];
            float c10 = sa[2 * kc + 1][0], c11 = sa[2 * kc + 1][1];
            float c12 = sa[2 * kc + 1][2], c13 = sa[2 * kc + 1][3];
            phf[kc][0] = pack2bf(c00, c01);
            phf[kc][1] = pack2bf(c02, c03);
            phf[kc][2] = pack2bf(c10, c11);
            phf[kc][3] = pack2bf(c12, c13);
#pragma unroll
            for (int r = 0; r < 4; r++) {
                __nv_bfloat162 hv = *(__nv_bfloat162*)&phf[kc][r];
                float2 hf = __bfloat1622float2(hv);
                float a0, a1;
                if (r == 0) { a0 = c00; a1 = c01; }
                else if (r == 1) { a0 = c02; a1 = c03; }
                else if (r == 2) { a0 = c10; a1 = c11; }
                else { a0 = c12; a1 = c13; }
                plf[kc][r] = pack2bf(a0 - hf.x, a1 - hf.y);
            }
        }

        // V(ts) ready (pending <= 1 leaves only K(ts+1))
        asm volatile("cp.async.wait_group 1;" ::: "memory");
        __syncthreads();   // V visible to all

        // ---- O += P V, 3-term, Vh deduped ---------------------------------
#pragma unroll
        for (int kc = 0; kc < 4; kc++) {
#pragma unroll
            for (int hp = 0; hp < 8; hp++) {
                unsigned bf[4];
                const unsigned voff = ((kc * 16 + vRow) * ATS + hp * 16 + vCol) * 2;
                LDSM4T(bf, smBase + 2 * PL + voff);  // Vh
                MMA_B16(oacc[2 * hp], phf[kc], bf[0], bf[1]);
                MMA_B16(oacc[2 * hp + 1], phf[kc], bf[2], bf[3]);
                MMA_B16(oacc[2 * hp], plf[kc], bf[0], bf[1]);
                MMA_B16(oacc[2 * hp + 1], plf[kc], bf[2], bf[3]);
                LDSM4T(bf, smBase + 3 * PL + voff);  // Vl
                MMA_B16(oacc[2 * hp], phf[kc], bf[0], bf[1]);
                MMA_B16(oacc[2 * hp + 1], phf[kc], bf[2], bf[3]);
            }
        }
        __syncthreads();   // all warps done reading V buffer
        if (ts + 1 < nTiles) ISSUE_V(ts + 1);
        asm volatile("cp.async.commit_group;" ::: "memory");
    }

    // Epilogue: normalize and write straight into g_a3 split-bf16 [hi|hi|lo]
    l0 += __shfl_xor_sync(0xffffffff, l0, 1);
    l0 += __shfl_xor_sync(0xffffffff, l0, 2);
    l1 += __shfl_xor_sync(0xffffffff, l1, 1);
    l1 += __shfl_xor_sync(0xffffffff, l1, 2);
    float inv0 = 1.f / l0, inv1 = 1.f / l1;
    const size_t row0 = (size_t)(b * Tn + tq * 64 + warp * 16 + gid);
#pragma unroll
    for (int nt = 0; nt < 16; nt++) {
        int h = n * HD + nt * 8 + tig * 2;
        float a0 = oacc[nt][0] * inv0, a1 = oacc[nt][1] * inv0;
        float b0v = oacc[nt][2] * inv1, b1v = oacc[nt][3] * inv1;
        unsigned hA = pack2bf(a0, a1);
        unsigned hB = pack2bf(b0v, b1v);
        __nv_bfloat162 hAv = *(__nv_bfloat162*)&hA;
        __nv_bfloat162 hBv = *(__nv_bfloat162*)&hB;
        float2 fA = __bfloat1622float2(hAv);
        float2 fB = __bfloat1622float2(hBv);
        unsigned lA = pack2bf(a0 - fA.x, a1 - fA.y);
        unsigned lB = pack2bf(b0v - fB.x, b1v - fB.y);
        __nv_bfloat16* r0p = g_a3 + row0 * K3 + h;
        __nv_bfloat16* r1p = g_a3 + (row0 + 8) * K3 + h;
        *(unsigned*)r0p = hA;
        *(unsigned*)(r0p + 2048) = hA;
        *(unsigned*)(r0p + 4096) = lA;
        *(unsigned*)r1p = hB;
        *(unsigned*)(r1p + 2048) = hB;
        *(unsigned*)(r1p + 4096) = lB;
    }
#undef ISSUE_K
#undef ISSUE_V
}

// ---------------------------------------------------------------------------
extern "C" void kernel_launch(void* const* d_in, const int* in_sizes, int n_in,
                              void* d_out, int out_size) {
    (void)in_sizes; (void)n_in; (void)out_size;
    const float* x = (const float*)d_in[0];
    const int* positions = (const int*)d_in[1];
    const float* w_q = (const float*)d_in[3];
    const float* w_kv = (const float*)d_in[4];
    const float* w_out = (const float*)d_in[5];
    float* out = (float*)d_out;

    const int gemm_smem = NSTG * STG_BY;    // 75776 bytes
    cudaFuncSetAttribute(attn_mma_kernel,
                         cudaFuncAttributeMaxDynamicSharedMemorySize, ATTN_SMEM);
    cudaFuncSetAttribute(bf3_gemm_kernel,
                         cudaFuncAttributeMaxDynamicSharedMemorySize, gemm_smem);

    void *p_qkv, *p_a3, *p_wb3, *p_wo3;
    cudaGetSymbolAddress(&p_qkv, g_qkv);
    cudaGetSymbolAddress(&p_a3, g_a3);
    cudaGetSymbolAddress(&p_wb3, g_wb3);
    cudaGetSymbolAddress(&p_wo3, g_wo3);

    {
        size_t total = (size_t)K3 * QKVN;
        pack_w3_kernel<<<(unsigned)((total + 255) / 256), 256>>>(w_q, w_kv);
    }
    {
        size_t total = (size_t)K3 * ENCN;
        pack_wo3_kernel<<<(unsigned)((total + 255) / 256), 256>>>(w_out);
    }
    {
        size_t total = (size_t)MROWS * 2048;
        split3_kernel<<<(unsigned)((total + 255) / 256), 256>>>(x);
    }
    {
        dim3 grid(QKVN / 128, MROWS / 128);
        bf3_gemm_kernel<<<grid, 256, gemm_smem>>>((const __nv_bfloat16*)p_a3,
                                                  (const __nv_bfloat16*)p_wb3,
                                                  (float*)p_qkv, QKVN);
    }
    {
        int total = MROWS * 2048;
        rope_split_kernel<<<(total + 255) / 256, 256>>>(positions);
    }
    {
        dim3 grid(Tn / 64, NHq, Bsz);  // (32, 16, 2)
        attn_mma_kernel<<<grid, 128, ATTN_SMEM>>>();
    }
    {
        dim3 grid(ENCN / 128, MROWS / 128);
        bf3_gemm_kernel<<<grid, 256, gemm_smem>>>((const __nv_bfloat16*)p_a3,
                                                  (const __nv_bfloat16*)p_wo3,
                                                  out, ENCN);
    }
}

// round 15
// speedup vs baseline: 1.1357x; 1.1357x over previous
#include <cuda_runtime.h>
#include <cuda_bf16.h>
#include <math.h>
#include <stdint.h>

// Problem constants
#define Bsz 2
#define Tn 2048
#define Dm 2048
#define NHq 16
#define NKV 8
#define HD 128
#define MROWS (Bsz * Tn)          // 4096 tokens
#define QKVN 4096                 // 2048 q | 1024 k | 1024 v
#define KOFF 2048
#define VOFF 3072
#define ENCN 2048
#define K3 6144                   // 3x split-bf16 K dimension
#define BIG_NEG -2.3819763e38f

// Scratch (device globals: allocation-free per harness rules)
__device__ __nv_bfloat16 g_wb3[(size_t)K3 * QKVN];  // QKV weights, [K3][N] split-bf16
__device__ __nv_bfloat16 g_wo3[(size_t)K3 * ENCN];  // out weights, [K3][N] split-bf16
__device__ __nv_bfloat16 g_a3[(size_t)MROWS * K3];  // activations, [M][K3] split-bf16
__device__ float g_qkv[(size_t)MROWS * QKVN];       // QKV projections (pre-rope)
__device__ __nv_bfloat16 g_sh[(size_t)MROWS * QKVN];  // rope'd qkv hi plane
__device__ __nv_bfloat16 g_sl[(size_t)MROWS * QKVN];  // rope'd qkv lo plane

// ---------------------------------------------------------------------------
#define CPA16(dst, src) \
    asm volatile("cp.async.cg.shared.global [%0], [%1], 16;" ::"r"(dst), "l"(src))
#define LDSM4(r, addr)                                                        \
    asm volatile("ldmatrix.sync.aligned.m8n8.x4.shared.b16 {%0,%1,%2,%3},[%4];" \
                 : "=r"((r)[0]), "=r"((r)[1]), "=r"((r)[2]), "=r"((r)[3])     \
                 : "r"(addr))
#define LDSM4T(r, addr)                                                       \
    asm volatile(                                                             \
        "ldmatrix.sync.aligned.m8n8.x4.trans.shared.b16 {%0,%1,%2,%3},[%4];"  \
        : "=r"((r)[0]), "=r"((r)[1]), "=r"((r)[2]), "=r"((r)[3])              \
        : "r"(addr))
#define MMA_B16(d, a, b0, b1)                                                 \
    asm volatile(                                                             \
        "mma.sync.aligned.m16n8k16.row.col.f32.bf16.bf16.f32 "                \
        "{%0,%1,%2,%3},{%4,%5,%6,%7},{%8,%9},{%0,%1,%2,%3};"                  \
        : "+f"((d)[0]), "+f"((d)[1]), "+f"((d)[2]), "+f"((d)[3])              \
        : "r"((a)[0]), "r"((a)[1]), "r"((a)[2]), "r"((a)[3]), "r"(b0), "r"(b1))

__device__ __forceinline__ unsigned pack2bf(float a, float b) {
    __nv_bfloat162 h = __floats2bfloat162_rn(a, b);
    return *(unsigned*)&h;
}

// ---------------------------------------------------------------------------
// Pack w_q + w_kv into split-bf16 [K3=6144][4096]: row blocks [hi | lo | hi]
// ---------------------------------------------------------------------------
__global__ void pack_w3_kernel(const float* __restrict__ wq,
                               const float* __restrict__ wkv) {
    size_t idx = (size_t)blockIdx.x * blockDim.x + threadIdx.x;
    if (idx >= (size_t)K3 * QKVN) return;
    int j = (int)(idx & (QKVN - 1));
    int k3 = (int)(idx >> 12);
    int seg = k3 >> 11;
    int d = k3 & 2047;
    float w;
    if (j < KOFF) {
        int n = j >> 7, h = j & 127;
        w = wq[((size_t)n * Dm + d) * HD + h];
    } else if (j < VOFF) {
        int jj = j - KOFF;
        int n = jj >> 7, h = jj & 127;
        w = wkv[((size_t)n * Dm + d) * HD + h];
    } else {
        int jj = j - VOFF;
        int n = jj >> 7, h = jj & 127;
        w = wkv[((size_t)(NKV + n) * Dm + d) * HD + h];
    }
    __nv_bfloat16 hi = __float2bfloat16(w);
    g_wb3[idx] = (seg == 1) ? __float2bfloat16(w - __bfloat162float(hi)) : hi;
}

__global__ void pack_wo3_kernel(const float* __restrict__ wout) {
    size_t idx = (size_t)blockIdx.x * blockDim.x + threadIdx.x;
    if (idx >= (size_t)K3 * ENCN) return;
    int d = (int)(idx & (ENCN - 1));
    int k3 = (int)(idx >> 11);
    int seg = k3 >> 11;
    int kk = k3 & 2047;
    float w = wout[(size_t)kk * ENCN + d];
    __nv_bfloat16 hi = __float2bfloat16(w);
    g_wo3[idx] = (seg == 1) ? __float2bfloat16(w - __bfloat162float(hi)) : hi;
}

// Split fp32 [4096][2048] into g_a3 [4096][6144]: cols [hi|hi|lo]
__global__ void split3_kernel(const float* __restrict__ src) {
    size_t idx = (size_t)blockIdx.x * blockDim.x + threadIdx.x;
    if (idx >= (size_t)MROWS * 2048) return;
    int k = (int)(idx & 2047);
    int m = (int)(idx >> 11);
    float a = src[idx];
    __nv_bfloat16 hi = __float2bfloat16(a);
    __nv_bfloat16 lo = __float2bfloat16(a - __bfloat162float(hi));
    __nv_bfloat16* dst = g_a3 + (size_t)m * K3;
    dst[k] = hi;
    dst[k + 2048] = hi;
    dst[k + 4096] = lo;
}

// ---------------------------------------------------------------------------
// Fused RoPE + hi/lo split: reads g_qkv fp32, writes g_sh/g_sl bf16 planes.
// ---------------------------------------------------------------------------
__device__ __forceinline__ void put_hl(size_t off, float v) {
    __nv_bfloat16 hi = __float2bfloat16(v);
    g_sh[off] = hi;
    g_sl[off] = __float2bfloat16(v - __bfloat162float(hi));
}

__global__ void rope_split_kernel(const int* __restrict__ positions) {
    int idx = blockIdx.x * blockDim.x + threadIdx.x;
    if (idx >= MROWS * 2048) return;
    int p = idx & 2047;
    int m = idx >> 11;
    size_t rowOff = (size_t)m * QKVN;
    if (p < 1536) {
        int head = p >> 6, pp = p & 63;
        float t = (float)positions[m];
        float frac = (float)(2 * pp) * (1.0f / 128.0f);
        float timescale = powf(10000.0f, frac);
        float ang = t / timescale;
        float s, c;
        sincosf(ang, &s, &c);
        int col = ((head < NHq) ? head * HD : KOFF + (head - NHq) * HD) + pp;
        float scale = (head < NHq) ? 0.08838834764831845f : 1.0f;
        const float* base = g_qkv + rowOff + col;
        float x1 = base[0], x2 = base[64];
        put_hl(rowOff + col, (x1 * c - x2 * s) * scale);
        put_hl(rowOff + col + 64, (x2 * c + x1 * s) * scale);
    } else {
        int col = VOFF + (p - 1536) * 2;
        put_hl(rowOff + col, g_qkv[rowOff + col]);
        put_hl(rowOff + col + 1, g_qkv[rowOff + col + 1]);
    }
}

// ---------------------------------------------------------------------------
// Split-bf16 GEMM (r5-proven config): 128x128x32 tile, 4-stage cp.async
// pipeline, wait_group 2, 256 threads, 2 CTAs/SM.
// ---------------------------------------------------------------------------
#define GBM 128
#define GBK 32
#define ASTR 40
#define BSTR 136
#define NSTG 4
#define A_BY (GBM * ASTR * 2)     // 10240
#define B_BY (GBK * BSTR * 2)     // 8704
#define STG_BY (A_BY + B_BY)      // 18944

#define GEMM_ISSUE(itv)                                                       \
    {                                                                         \
        const int k0 = (itv) * GBK;                                           \
        const unsigned aOff = smBase + ((itv) % NSTG) * STG_BY;               \
        const unsigned bOff = aOff + A_BY;                                    \
        CPA16(aOff + (arow * ASTR + ach) * 2,                                 \
              A + (size_t)(rowBlock + arow) * K3 + k0 + ach);                 \
        CPA16(aOff + ((arow + 64) * ASTR + ach) * 2,                          \
              A + (size_t)(rowBlock + arow + 64) * K3 + k0 + ach);            \
        CPA16(bOff + (brow * BSTR + bch) * 2,                                 \
              B + (size_t)(k0 + brow) * N + colBlock + bch);                  \
        CPA16(bOff + ((brow + 16) * BSTR + bch) * 2,                          \
              B + (size_t)(k0 + brow + 16) * N + colBlock + bch);             \
        asm volatile("cp.async.commit_group;");                               \
    }

__global__ __launch_bounds__(256, 2) void bf3_gemm_kernel(
    const __nv_bfloat16* __restrict__ A, const __nv_bfloat16* __restrict__ B,
    float* __restrict__ C, int N) {
    extern __shared__ __align__(16) char gsm[];
    const unsigned smBase = (unsigned)__cvta_generic_to_shared(gsm);
    const int tid = threadIdx.x;
    const int lane = tid & 31, warp = tid >> 5;
    const int warpM = warp >> 1, warpN = warp & 1;
    const int rowBlock = blockIdx.y * GBM, colBlock = blockIdx.x * 128;

    const int arow = tid >> 2, ach = (tid & 3) * 8;
    const int brow = tid >> 4, bch = (tid & 15) * 8;

    const int NIT = K3 / GBK;  // 192
    GEMM_ISSUE(0);
    GEMM_ISSUE(1);
    GEMM_ISSUE(2);

    float acc[2][8][4] = {};
    const int ldRow = (lane & 7) + ((lane >> 3) & 1) * 8;
    const int ldCol = (lane >> 4) * 8;

    for (int it = 0; it < NIT; it++) {
        asm volatile("cp.async.wait_group 2;" ::: "memory");
        __syncthreads();
        if (it + NSTG - 1 < NIT) GEMM_ISSUE(it + NSTG - 1);

        const unsigned aOff = smBase + (it % NSTG) * STG_BY;
        const unsigned bOff = aOff + A_BY;
#pragma unroll
        for (int ks = 0; ks < 2; ks++) {
            unsigned af[2][4];
#pragma unroll
            for (int mt = 0; mt < 2; mt++) {
                unsigned addr =
                    aOff + ((warpM * 32 + mt * 16 + ldRow) * ASTR + ks * 16 + ldCol) * 2;
                LDSM4(af[mt], addr);
            }
            unsigned bfr[8][2];
#pragma unroll
            for (int np = 0; np < 4; np++) {
                unsigned addr =
                    bOff + ((ks * 16 + ldRow) * BSTR + warpN * 64 + np * 16 + ldCol) * 2;
                asm volatile(
                    "ldmatrix.sync.aligned.m8n8.x4.trans.shared.b16 {%0,%1,%2,%3}, [%4];"
                    : "=r"(bfr[np * 2][0]), "=r"(bfr[np * 2][1]),
                      "=r"(bfr[np * 2 + 1][0]), "=r"(bfr[np * 2 + 1][1])
                    : "r"(addr));
            }
#pragma unroll
            for (int mt = 0; mt < 2; mt++)
#pragma unroll
                for (int nt = 0; nt < 8; nt++)
                    MMA_B16(acc[mt][nt], af[mt], bfr[nt][0], bfr[nt][1]);
        }
    }

    const int gid = lane >> 2, tig = lane & 3;
#pragma unroll
    for (int mt = 0; mt < 2; mt++) {
        int r0 = rowBlock + warpM * 32 + mt * 16 + gid;
#pragma unroll
        for (int nt = 0; nt < 8; nt++) {
            int c = colBlock + warpN * 64 + nt * 8 + tig * 2;
            *(float2*)&C[(size_t)r0 * N + c] =
                make_float2(acc[mt][nt][0], acc[mt][nt][1]);
            *(float2*)&C[(size_t)(r0 + 8) * N + c] =
                make_float2(acc[mt][nt][2], acc[mt][nt][3]);
        }
    }
}

// ---------------------------------------------------------------------------
// Tensor-core flash attention (r13 geometry), split-bf16 3-term, LDSM-deduped,
// FIXED-MAX softmax: softcap bounds logits to +/-50, so use m = 50 always.
// p = exp(v - 50); probs = p / sum(p). No running max, no shuffles in the
// loop, no accumulator rescale. Masked lanes: exp(BIG_NEG - 50) = 0.
// CTA: 128 q-rows x 1 head x 1 batch; 256 threads (8 warps x 16 rows).
// ---------------------------------------------------------------------------
#define ATS 136
#define ABUF (64 * ATS)
#define ASTG (4 * ABUF)
#define ATTN_SMEM (2 * ASTG * 2)

__global__ __launch_bounds__(256, 1) void attn_mma_kernel() {
    extern __shared__ __align__(16) __nv_bfloat16 sm[];
    const int tid = threadIdx.x, lane = tid & 31, warp = tid >> 5;
    const int tq = 15 - blockIdx.x;
    const int n = blockIdx.y, b = blockIdx.z, kvh = n >> 1;
    const unsigned smBase = (unsigned)__cvta_generic_to_shared(sm);

    const int kvRow = tid >> 2;
    const int kvCh = (tid & 3) * 32;
    const int qRow = tid >> 1;
    const int qCh = (tid & 1) * 64;

    const size_t kRowBase = (size_t)(b * Tn) * QKVN + KOFF + kvh * HD;
    const size_t vRowBase = (size_t)(b * Tn) * QKVN + VOFF + kvh * HD;

    {
        size_t qsrc = (size_t)(b * Tn + tq * 128 + qRow) * QKVN + n * HD + qCh;
#pragma unroll
        for (int c = 0; c < 8; c++) {
            CPA16(smBase + (ASTG + qRow * ATS + qCh + c * 8) * 2, g_sh + qsrc + c * 8);
            CPA16(smBase + (ASTG + 2 * ABUF + qRow * ATS + qCh + c * 8) * 2,
                  g_sl + qsrc + c * 8);
        }
        size_t kr = kRowBase + (size_t)kvRow * QKVN + kvCh;
        size_t vr = vRowBase + (size_t)kvRow * QKVN + kvCh;
#pragma unroll
        for (int c = 0; c < 4; c++) {
            CPA16(smBase + (0 * ABUF + kvRow * ATS + kvCh + c * 8) * 2, g_sh + kr + c * 8);
            CPA16(smBase + (1 * ABUF + kvRow * ATS + kvCh + c * 8) * 2, g_sl + kr + c * 8);
            CPA16(smBase + (2 * ABUF + kvRow * ATS + kvCh + c * 8) * 2, g_sh + vr + c * 8);
            CPA16(smBase + (3 * ABUF + kvRow * ATS + kvCh + c * 8) * 2, g_sl + vr + c * 8);
        }
        asm volatile("cp.async.commit_group;");
    }
    asm volatile("cp.async.wait_group 0;" ::: "memory");
    __syncthreads();

    unsigned qfH[8][4], qfL[8][4];
    {
        const int aRow = lane & 15;
        const int aCol = (lane >> 4) * 8;
#pragma unroll
        for (int kc = 0; kc < 8; kc++) {
            LDSM4(qfH[kc],
                  smBase + (ASTG + (warp * 16 + aRow) * ATS + kc * 16 + aCol) * 2);
            LDSM4(qfL[kc],
                  smBase + (ASTG + 2 * ABUF + (warp * 16 + aRow) * ATS + kc * 16 + aCol) * 2);
        }
    }
    __syncthreads();  // Q region may now be overwritten by prefetch

    float oacc[16][4] = {};
    float l0 = 0.f, l1 = 0.f;
    const int gid = lane >> 2, tig = lane & 3;
    const int gr0 = tq * 128 + warp * 16 + gid;

    const int bkRow = ((lane >> 4) & 1) * 8 + (lane & 7);
    const int bkCol = ((lane >> 3) & 1) * 8;
    const int vRow = ((lane >> 3) & 1) * 8 + (lane & 7);
    const int vCol = ((lane >> 4) & 1) * 8;

    const int nTiles = 2 * tq + 2;
    for (int ts = 0; ts < nTiles; ts++) {
        const int stage = ts & 1;
        const unsigned stg = smBase + stage * (ASTG * 2);
        if (ts > 0) {
            asm volatile("cp.async.wait_group 0;" ::: "memory");
            __syncthreads();
        }
        if (ts + 1 < nTiles) {
            const unsigned pst = smBase + (stage ^ 1) * (ASTG * 2);
            size_t kr = kRowBase + (size_t)((ts + 1) * 64 + kvRow) * QKVN + kvCh;
            size_t vr = vRowBase + (size_t)((ts + 1) * 64 + kvRow) * QKVN + kvCh;
#pragma unroll
            for (int c = 0; c < 4; c++) {
                CPA16(pst + (0 * ABUF + kvRow * ATS + kvCh + c * 8) * 2, g_sh + kr + c * 8);
                CPA16(pst + (1 * ABUF + kvRow * ATS + kvCh + c * 8) * 2, g_sl + kr + c * 8);
                CPA16(pst + (2 * ABUF + kvRow * ATS + kvCh + c * 8) * 2, g_sh + vr + c * 8);
                CPA16(pst + (3 * ABUF + kvRow * ATS + kvCh + c * 8) * 2, g_sl + vr + c * 8);
            }
            asm volatile("cp.async.commit_group;");
        }

        // S = softcap(Q K^T) 3-term: each Kh frag feeds Qh AND Ql MMAs;
        // Kl frag feeds Qh only. sa = QhKh + QlKh + QhKl.
        float sa[8][4] = {};
#pragma unroll
        for (int kc = 0; kc < 8; kc++) {
#pragma unroll
            for (int ntp = 0; ntp < 4; ntp++) {
                unsigned bf[4];
                const unsigned boff = ((ntp * 16 + bkRow) * ATS + kc * 16 + bkCol) * 2;
                LDSM4(bf, stg + boff);                // Kh
                MMA_B16(sa[2 * ntp], qfH[kc], bf[0], bf[1]);
                MMA_B16(sa[2 * ntp + 1], qfH[kc], bf[2], bf[3]);
                MMA_B16(sa[2 * ntp], qfL[kc], bf[0], bf[1]);
                MMA_B16(sa[2 * ntp + 1], qfL[kc], bf[2], bf[3]);
                LDSM4(bf, stg + ABUF * 2 + boff);     // Kl
                MMA_B16(sa[2 * ntp], qfH[kc], bf[0], bf[1]);
                MMA_B16(sa[2 * ntp + 1], qfH[kc], bf[2], bf[3]);
            }
        }

        // Softcap + causal mask + fixed-max exp: p = exp(v - 50)
        const bool needMask = (ts * 64 + 63) > (tq * 128 + warp * 16);
#pragma unroll
        for (int nt = 0; nt < 8; nt++) {
#pragma unroll
            for (int j = 0; j < 4; j++) {
                float x = fminf(fmaxf(sa[nt][j] * 0.02f, -8.f), 8.f);
                float e = __expf(2.f * x);
                float v = 50.f * __fdividef(e - 1.f, e + 1.f);
                if (needMask) {
                    int gc = ts * 64 + nt * 8 + tig * 2 + (j & 1);
                    int gr = gr0 + ((j >= 2) ? 8 : 0);
                    if (gc > gr) v = BIG_NEG;
                }
                float p = __expf(v - 50.f);
                sa[nt][j] = p;
                if (j < 2) l0 += p;
                else       l1 += p;
            }
        }

        // Pack P into A fragments (hi + lo)
        unsigned phf[4][4], plf[4][4];
#pragma unroll
        for (int kc = 0; kc < 4; kc++) {
            float c00 = sa[2 * kc][0], c01 = sa[2 * kc][1];
            float c02 = sa[2 * kc][2], c03 = sa[2 * kc][3];
            float c10 = sa[2 * kc + 1][0], c11 = sa[2 * kc + 1][1];
            float c12 = sa[2 * kc + 1][2], c13 = sa[2 * kc + 1][3];
            phf[kc][0] = pack2bf(c00, c01);
            phf[kc][1] = pack2bf(c02, c03);
            phf[kc][2] = pack2bf(c10, c11);
            phf[kc][3] = pack2bf(c12, c13);
#pragma unroll
            for (int r = 0; r < 4; r++) {
                __nv_bfloat162 hv = *(__nv_bfloat162*)&phf[kc][r];
                float2 hf = __bfloat1622float2(hv);
                float a0, a1;
                if (r == 0) { a0 = c00; a1 = c01; }
                else if (r == 1) { a0 = c02; a1 = c03; }
                else if (r == 2) { a0 = c10; a1 = c11; }
                else { a0 = c12; a1 = c13; }
                plf[kc][r] = pack2bf(a0 - hf.x, a1 - hf.y);
            }
        }

        // O += P V 3-term: each Vh frag feeds Ph AND Pl MMAs; Vl feeds Ph.
        // oacc = PhVh + PlVh + PhVl. Byte offsets: Vh @ ABUF*4, Vl @ ABUF*6.
#pragma unroll
        for (int kc = 0; kc < 4; kc++) {
#pragma unroll
            for (int hp = 0; hp < 8; hp++) {
                unsigned bf[4];
                const unsigned voff = ((kc * 16 + vRow) * ATS + hp * 16 + vCol) * 2;
                LDSM4T(bf, stg + ABUF * 4 + voff);    // Vh
                MMA_B16(oacc[2 * hp], phf[kc], bf[0], bf[1]);
                MMA_B16(oacc[2 * hp + 1], phf[kc], bf[2], bf[3]);
                MMA_B16(oacc[2 * hp], plf[kc], bf[0], bf[1]);
                MMA_B16(oacc[2 * hp + 1], plf[kc], bf[2], bf[3]);
                LDSM4T(bf, stg + ABUF * 6 + voff);    // Vl
                MMA_B16(oacc[2 * hp], phf[kc], bf[0], bf[1]);
                MMA_B16(oacc[2 * hp + 1], phf[kc], bf[2], bf[3]);
            }
        }
        // (end-of-loop __syncthreads removed; top-of-iter wait+sync suffices)
    }

    // Epilogue: reduce l across the 4-lane row group, normalize, write g_a3
    l0 += __shfl_xor_sync(0xffffffff, l0, 1);
    l0 += __shfl_xor_sync(0xffffffff, l0, 2);
    l1 += __shfl_xor_sync(0xffffffff, l1, 1);
    l1 += __shfl_xor_sync(0xffffffff, l1, 2);
    float inv0 = 1.f / l0, inv1 = 1.f / l1;
    const size_t row0 = (size_t)(b * Tn + tq * 128 + warp * 16 + gid);
#pragma unroll
    for (int nt = 0; nt < 16; nt++) {
        int h = n * HD + nt * 8 + tig * 2;
        float a0 = oacc[nt][0] * inv0, a1 = oacc[nt][1] * inv0;
        float b0v = oacc[nt][2] * inv1, b1v = oacc[nt][3] * inv1;
        unsigned hA = pack2bf(a0, a1);
        unsigned hB = pack2bf(b0v, b1v);
        __nv_bfloat162 hAv = *(__nv_bfloat162*)&hA;
        __nv_bfloat162 hBv = *(__nv_bfloat162*)&hB;
        float2 fA = __bfloat1622float2(hAv);
        float2 fB = __bfloat1622float2(hBv);
        unsigned lA = pack2bf(a0 - fA.x, a1 - fA.y);
        unsigned lB = pack2bf(b0v - fB.x, b1v - fB.y);
        __nv_bfloat16* r0p = g_a3 + row0 * K3 + h;
        __nv_bfloat16* r1p = g_a3 + (row0 + 8) * K3 + h;
        *(unsigned*)r0p = hA;
        *(unsigned*)(r0p + 2048) = hA;
        *(unsigned*)(r0p + 4096) = lA;
        *(unsigned*)r1p = hB;
        *(unsigned*)(r1p + 2048) = hB;
        *(unsigned*)(r1p + 4096) = lB;
    }
}

// ---------------------------------------------------------------------------
extern "C" void kernel_launch(void* const* d_in, const int* in_sizes, int n_in,
                              void* d_out, int out_size) {
    (void)in_sizes; (void)n_in; (void)out_size;
    const float* x = (const float*)d_in[0];
    const int* positions = (const int*)d_in[1];
    const float* w_q = (const float*)d_in[3];
    const float* w_kv = (const float*)d_in[4];
    const float* w_out = (const float*)d_in[5];
    float* out = (float*)d_out;

    const int gemm_smem = NSTG * STG_BY;    // 75776 bytes
    cudaFuncSetAttribute(attn_mma_kernel,
                         cudaFuncAttributeMaxDynamicSharedMemorySize, ATTN_SMEM);
    cudaFuncSetAttribute(bf3_gemm_kernel,
                         cudaFuncAttributeMaxDynamicSharedMemorySize, gemm_smem);

    void *p_qkv, *p_a3, *p_wb3, *p_wo3;
    cudaGetSymbolAddress(&p_qkv, g_qkv);
    cudaGetSymbolAddress(&p_a3, g_a3);
    cudaGetSymbolAddress(&p_wb3, g_wb3);
    cudaGetSymbolAddress(&p_wo3, g_wo3);

    {
        size_t total = (size_t)K3 * QKVN;
        pack_w3_kernel<<<(unsigned)((total + 255) / 256), 256>>>(w_q, w_kv);
    }
    {
        size_t total = (size_t)K3 * ENCN;
        pack_wo3_kernel<<<(unsigned)((total + 255) / 256), 256>>>(w_out);
    }
    {
        size_t total = (size_t)MROWS * 2048;
        split3_kernel<<<(unsigned)((total + 255) / 256), 256>>>(x);
    }
    {
        dim3 grid(QKVN / 128, MROWS / 128);
        bf3_gemm_kernel<<<grid, 256, gemm_smem>>>((const __nv_bfloat16*)p_a3,
                                                  (const __nv_bfloat16*)p_wb3,
                                                  (float*)p_qkv, QKVN);
    }
    {
        int total = MROWS * 2048;
        rope_split_kernel<<<(total + 255) / 256, 256>>>(positions);
    }
    {
        dim3 grid(Tn / 128, NHq, Bsz);
        attn_mma_kernel<<<grid, 256, ATTN_SMEM>>>();
    }
    {
        dim3 grid(ENCN / 128, MROWS / 128);
        bf3_gemm_kernel<<<grid, 256, gemm_smem>>>((const __nv_bfloat16*)p_a3,
                                                  (const __nv_bfloat16*)p_wo3,
                                                  out, ENCN);
    }
}

// round 16
// speedup vs baseline: 1.1453x; 1.0084x over previous
#include <cuda_runtime.h>
#include <cuda_bf16.h>
#include <math.h>
#include <stdint.h>

// Problem constants
#define Bsz 2
#define Tn 2048
#define Dm 2048
#define NHq 16
#define NKV 8
#define HD 128
#define MROWS (Bsz * Tn)          // 4096 tokens
#define QKVN 4096                 // 2048 q | 1024 k | 1024 v
#define KOFF 2048
#define VOFF 3072
#define ENCN 2048
#define K3 6144                   // 3x split-bf16 K dimension
#define BIG_NEG -2.3819763e38f

// Scratch (device globals: allocation-free per harness rules)
__device__ __nv_bfloat16 g_wb3[(size_t)K3 * QKVN];  // QKV weights, [K3][N] split-bf16
__device__ __nv_bfloat16 g_wo3[(size_t)K3 * ENCN];  // out weights, [K3][N] split-bf16
__device__ __nv_bfloat16 g_a3[(size_t)MROWS * K3];  // activations, [M][K3] split-bf16
__device__ __nv_bfloat16 g_sh[(size_t)MROWS * QKVN];  // rope'd qkv hi plane
__device__ __nv_bfloat16 g_sl[(size_t)MROWS * QKVN];  // rope'd qkv lo plane

// ---------------------------------------------------------------------------
#define CPA16(dst, src) \
    asm volatile("cp.async.cg.shared.global [%0], [%1], 16;" ::"r"(dst), "l"(src))
#define LDSM4(r, addr)                                                        \
    asm volatile("ldmatrix.sync.aligned.m8n8.x4.shared.b16 {%0,%1,%2,%3},[%4];" \
                 : "=r"((r)[0]), "=r"((r)[1]), "=r"((r)[2]), "=r"((r)[3])     \
                 : "r"(addr))
#define LDSM4T(r, addr)                                                       \
    asm volatile(                                                             \
        "ldmatrix.sync.aligned.m8n8.x4.trans.shared.b16 {%0,%1,%2,%3},[%4];"  \
        : "=r"((r)[0]), "=r"((r)[1]), "=r"((r)[2]), "=r"((r)[3])              \
        : "r"(addr))
#define MMA_B16(d, a, b0, b1)                                                 \
    asm volatile(                                                             \
        "mma.sync.aligned.m16n8k16.row.col.f32.bf16.bf16.f32 "                \
        "{%0,%1,%2,%3},{%4,%5,%6,%7},{%8,%9},{%0,%1,%2,%3};"                  \
        : "+f"((d)[0]), "+f"((d)[1]), "+f"((d)[2]), "+f"((d)[3])              \
        : "r"((a)[0]), "r"((a)[1]), "r"((a)[2]), "r"((a)[3]), "r"(b0), "r"(b1))

__device__ __forceinline__ unsigned pack2bf(float a, float b) {
    __nv_bfloat162 h = __floats2bfloat162_rn(a, b);
    return *(unsigned*)&h;
}

// Write packed hi + lo (2 elems) to g_sh/g_sl
__device__ __forceinline__ void put_hl2(__nv_bfloat16* dsh, __nv_bfloat16* dsl,
                                        float a, float b) {
    unsigned h = pack2bf(a, b);
    __nv_bfloat162 hv = *(__nv_bfloat162*)&h;
    float2 f = __bfloat1622float2(hv);
    unsigned l = pack2bf(a - f.x, b - f.y);
    *(unsigned*)dsh = h;
    *(unsigned*)dsl = l;
}

// ---------------------------------------------------------------------------
// Pack w_q + w_kv into split-bf16 [K3=6144][4096], single-read:
// each (d, j) element read once, 3 stores (hi @ seg0, lo @ seg1, hi @ seg2).
// ---------------------------------------------------------------------------
__global__ void pack_w3_kernel(const float* __restrict__ wq,
                               const float* __restrict__ wkv) {
    size_t idx = (size_t)blockIdx.x * blockDim.x + threadIdx.x;
    if (idx >= (size_t)Dm * QKVN) return;
    int j = (int)(idx & (QKVN - 1));
    int d = (int)(idx >> 12);
    float w;
    if (j < KOFF) {
        int n = j >> 7, h = j & 127;
        w = wq[((size_t)n * Dm + d) * HD + h];
    } else if (j < VOFF) {
        int jj = j - KOFF;
        int n = jj >> 7, h = jj & 127;
        w = wkv[((size_t)n * Dm + d) * HD + h];
    } else {
        int jj = j - VOFF;
        int n = jj >> 7, h = jj & 127;
        w = wkv[((size_t)(NKV + n) * Dm + d) * HD + h];
    }
    __nv_bfloat16 hi = __float2bfloat16(w);
    __nv_bfloat16 lo = __float2bfloat16(w - __bfloat162float(hi));
    g_wb3[(size_t)d * QKVN + j] = hi;
    g_wb3[(size_t)(d + 2048) * QKVN + j] = lo;
    g_wb3[(size_t)(d + 4096) * QKVN + j] = hi;
}

__global__ void pack_wo3_kernel(const float* __restrict__ wout) {
    size_t idx = (size_t)blockIdx.x * blockDim.x + threadIdx.x;
    if (idx >= (size_t)Dm * ENCN) return;
    int j = (int)(idx & (ENCN - 1));
    int kk = (int)(idx >> 11);
    float w = wout[(size_t)kk * ENCN + j];
    __nv_bfloat16 hi = __float2bfloat16(w);
    __nv_bfloat16 lo = __float2bfloat16(w - __bfloat162float(hi));
    g_wo3[(size_t)kk * ENCN + j] = hi;
    g_wo3[(size_t)(kk + 2048) * ENCN + j] = lo;
    g_wo3[(size_t)(kk + 4096) * ENCN + j] = hi;
}

// Split fp32 [4096][2048] into g_a3 [4096][6144]: cols [hi|hi|lo]
__global__ void split3_kernel(const float* __restrict__ src) {
    size_t idx = (size_t)blockIdx.x * blockDim.x + threadIdx.x;
    if (idx >= (size_t)MROWS * 2048) return;
    int k = (int)(idx & 2047);
    int m = (int)(idx >> 11);
    float a = src[idx];
    __nv_bfloat16 hi = __float2bfloat16(a);
    __nv_bfloat16 lo = __float2bfloat16(a - __bfloat162float(hi));
    __nv_bfloat16* dst = g_a3 + (size_t)m * K3;
    dst[k] = hi;
    dst[k + 2048] = hi;
    dst[k + 4096] = lo;
}

// ---------------------------------------------------------------------------
// Split-bf16 GEMM (r5-proven core): 128x128x32 tile, 4-stage cp.async,
// wait_group 2, 256 threads, 2 CTAs/SM.
// fuseRope=1 (QKV proj): epilogue stages acc tile in smem, applies RoPE
// (q/k col-blocks) or plain copy (v), and writes split-bf16 g_sh/g_sl
// directly — the fp32 intermediate and rope_split kernel are gone.
// fuseRope=0 (out proj): plain fp32 writeback to C.
// ---------------------------------------------------------------------------
#define GBM 128
#define GBK 32
#define ASTR 40
#define BSTR 136
#define NSTG 4
#define A_BY (GBM * ASTR * 2)     // 10240
#define B_BY (GBK * BSTR * 2)     // 8704
#define STG_BY (A_BY + B_BY)      // 18944
#define EPI_TS 130                // fp32 epilogue tile stride (floats)

#define GEMM_ISSUE(itv)                                                       \
    {                                                                         \
        const int k0 = (itv) * GBK;                                           \
        const unsigned aOff = smBase + ((itv) % NSTG) * STG_BY;               \
        const unsigned bOff = aOff + A_BY;                                    \
        CPA16(aOff + (arow * ASTR + ach) * 2,                                 \
              A + (size_t)(rowBlock + arow) * K3 + k0 + ach);                 \
        CPA16(aOff + ((arow + 64) * ASTR + ach) * 2,                          \
              A + (size_t)(rowBlock + arow + 64) * K3 + k0 + ach);            \
        CPA16(bOff + (brow * BSTR + bch) * 2,                                 \
              B + (size_t)(k0 + brow) * N + colBlock + bch);                  \
        CPA16(bOff + ((brow + 16) * BSTR + bch) * 2,                          \
              B + (size_t)(k0 + brow + 16) * N + colBlock + bch);             \
        asm volatile("cp.async.commit_group;");                               \
    }

__global__ __launch_bounds__(256, 2) void bf3_gemm_kernel(
    const __nv_bfloat16* __restrict__ A, const __nv_bfloat16* __restrict__ B,
    float* __restrict__ C, int N, const int* __restrict__ positions,
    int fuseRope) {
    extern __shared__ __align__(16) char gsm[];
    const unsigned smBase = (unsigned)__cvta_generic_to_shared(gsm);
    const int tid = threadIdx.x;
    const int lane = tid & 31, warp = tid >> 5;
    const int warpM = warp >> 1, warpN = warp & 1;
    const int rowBlock = blockIdx.y * GBM, colBlock = blockIdx.x * 128;

    const int arow = tid >> 2, ach = (tid & 3) * 8;
    const int brow = tid >> 4, bch = (tid & 15) * 8;

    const int NIT = K3 / GBK;  // 192
    GEMM_ISSUE(0);
    GEMM_ISSUE(1);
    GEMM_ISSUE(2);

    float acc[2][8][4] = {};
    const int ldRow = (lane & 7) + ((lane >> 3) & 1) * 8;
    const int ldCol = (lane >> 4) * 8;

    for (int it = 0; it < NIT; it++) {
        asm volatile("cp.async.wait_group 2;" ::: "memory");
        __syncthreads();
        if (it + NSTG - 1 < NIT) GEMM_ISSUE(it + NSTG - 1);

        const unsigned aOff = smBase + (it % NSTG) * STG_BY;
        const unsigned bOff = aOff + A_BY;
#pragma unroll
        for (int ks = 0; ks < 2; ks++) {
            unsigned af[2][4];
#pragma unroll
            for (int mt = 0; mt < 2; mt++) {
                unsigned addr =
                    aOff + ((warpM * 32 + mt * 16 + ldRow) * ASTR + ks * 16 + ldCol) * 2;
                LDSM4(af[mt], addr);
            }
            unsigned bfr[8][2];
#pragma unroll
            for (int np = 0; np < 4; np++) {
                unsigned addr =
                    bOff + ((ks * 16 + ldRow) * BSTR + warpN * 64 + np * 16 + ldCol) * 2;
                asm volatile(
                    "ldmatrix.sync.aligned.m8n8.x4.trans.shared.b16 {%0,%1,%2,%3}, [%4];"
                    : "=r"(bfr[np * 2][0]), "=r"(bfr[np * 2][1]),
                      "=r"(bfr[np * 2 + 1][0]), "=r"(bfr[np * 2 + 1][1])
                    : "r"(addr));
            }
#pragma unroll
            for (int mt = 0; mt < 2; mt++)
#pragma unroll
                for (int nt = 0; nt < 8; nt++)
                    MMA_B16(acc[mt][nt], af[mt], bfr[nt][0], bfr[nt][1]);
        }
    }

    const int gid = lane >> 2, tig = lane & 3;

    if (!fuseRope) {
        // Plain fp32 writeback
#pragma unroll
        for (int mt = 0; mt < 2; mt++) {
            int r0 = rowBlock + warpM * 32 + mt * 16 + gid;
#pragma unroll
            for (int nt = 0; nt < 8; nt++) {
                int c = colBlock + warpN * 64 + nt * 8 + tig * 2;
                *(float2*)&C[(size_t)r0 * N + c] =
                    make_float2(acc[mt][nt][0], acc[mt][nt][1]);
                *(float2*)&C[(size_t)(r0 + 8) * N + c] =
                    make_float2(acc[mt][nt][2], acc[mt][nt][3]);
            }
        }
        return;
    }

    // ---- Fused RoPE + hi/lo split epilogue (QKV projection) ---------------
    // Drain pipeline, then reuse stage smem as fp32 tile [128][EPI_TS].
    asm volatile("cp.async.wait_group 0;" ::: "memory");
    __syncthreads();
    float* tile = (float*)gsm;
#pragma unroll
    for (int mt = 0; mt < 2; mt++) {
        int r0 = warpM * 32 + mt * 16 + gid;
#pragma unroll
        for (int nt = 0; nt < 8; nt++) {
            int c = warpN * 64 + nt * 8 + tig * 2;
            *(float2*)&tile[r0 * EPI_TS + c] =
                make_float2(acc[mt][nt][0], acc[mt][nt][1]);
            *(float2*)&tile[(r0 + 8) * EPI_TS + c] =
                make_float2(acc[mt][nt][2], acc[mt][nt][3]);
        }
    }
    __syncthreads();

    const int row = tid >> 1;                 // 0..127
    const size_t grow = (size_t)(rowBlock + row);
    __nv_bfloat16* dsh = g_sh + grow * QKVN + colBlock;
    __nv_bfloat16* dsl = g_sl + grow * QKVN + colBlock;
    const float* trow = tile + row * EPI_TS;

    if (blockIdx.x < 24) {                    // q (bx<16) or k (16..23): rope
        const float t = (float)positions[grow];
        const float scale = (blockIdx.x < 16) ? 0.08838834764831845f : 1.0f;
        const int p0 = (tid & 1) * 32;
#pragma unroll 4
        for (int p = p0; p < p0 + 32; p += 2) {
            float o1a, o2a, o1b, o2b;
            {
                float frac = (float)(2 * p) * (1.0f / 128.0f);
                float tsc = powf(10000.0f, frac);
                float ang = t / tsc;
                float s, c;
                sincosf(ang, &s, &c);
                float x1 = trow[p], x2 = trow[p + 64];
                o1a = (x1 * c - x2 * s) * scale;
                o2a = (x2 * c + x1 * s) * scale;
            }
            {
                float frac = (float)(2 * (p + 1)) * (1.0f / 128.0f);
                float tsc = powf(10000.0f, frac);
                float ang = t / tsc;
                float s, c;
                sincosf(ang, &s, &c);
                float x1 = trow[p + 1], x2 = trow[p + 65];
                o1b = (x1 * c - x2 * s) * scale;
                o2b = (x2 * c + x1 * s) * scale;
            }
            put_hl2(dsh + p, dsl + p, o1a, o1b);
            put_hl2(dsh + p + 64, dsl + p + 64, o2a, o2b);
        }
    } else {                                  // v: plain split
        const int c0 = (tid & 1) * 64;
#pragma unroll 8
        for (int c = c0; c < c0 + 64; c += 2)
            put_hl2(dsh + c, dsl + c, trow[c], trow[c + 1]);
    }
}

// ---------------------------------------------------------------------------
// Tensor-core flash attention (r13 geometry), split-bf16 3-term, LDSM-deduped,
// fixed-max softmax with clamp-free softcap:
//   p = exp(50*tanh(s/50) - 50) = exp(-100 / (exp(s/25) + 1))
// saturates correctly through inf/0 so no clamp needed; masked -> p = 0.
// CTA: 128 q-rows x 1 head x 1 batch; 256 threads (8 warps x 16 rows).
// ---------------------------------------------------------------------------
#define ATS 136
#define ABUF (64 * ATS)
#define ASTG (4 * ABUF)
#define ATTN_SMEM (2 * ASTG * 2)

__global__ __launch_bounds__(256, 1) void attn_mma_kernel() {
    extern __shared__ __align__(16) __nv_bfloat16 sm[];
    const int tid = threadIdx.x, lane = tid & 31, warp = tid >> 5;
    const int tq = 15 - blockIdx.x;
    const int n = blockIdx.y, b = blockIdx.z, kvh = n >> 1;
    const unsigned smBase = (unsigned)__cvta_generic_to_shared(sm);

    const int kvRow = tid >> 2;
    const int kvCh = (tid & 3) * 32;
    const int qRow = tid >> 1;
    const int qCh = (tid & 1) * 64;

    const size_t kRowBase = (size_t)(b * Tn) * QKVN + KOFF + kvh * HD;
    const size_t vRowBase = (size_t)(b * Tn) * QKVN + VOFF + kvh * HD;

    {
        size_t qsrc = (size_t)(b * Tn + tq * 128 + qRow) * QKVN + n * HD + qCh;
#pragma unroll
        for (int c = 0; c < 8; c++) {
            CPA16(smBase + (ASTG + qRow * ATS + qCh + c * 8) * 2, g_sh + qsrc + c * 8);
            CPA16(smBase + (ASTG + 2 * ABUF + qRow * ATS + qCh + c * 8) * 2,
                  g_sl + qsrc + c * 8);
        }
        size_t kr = kRowBase + (size_t)kvRow * QKVN + kvCh;
        size_t vr = vRowBase + (size_t)kvRow * QKVN + kvCh;
#pragma unroll
        for (int c = 0; c < 4; c++) {
            CPA16(smBase + (0 * ABUF + kvRow * ATS + kvCh + c * 8) * 2, g_sh + kr + c * 8);
            CPA16(smBase + (1 * ABUF + kvRow * ATS + kvCh + c * 8) * 2, g_sl + kr + c * 8);
            CPA16(smBase + (2 * ABUF + kvRow * ATS + kvCh + c * 8) * 2, g_sh + vr + c * 8);
            CPA16(smBase + (3 * ABUF + kvRow * ATS + kvCh + c * 8) * 2, g_sl + vr + c * 8);
        }
        asm volatile("cp.async.commit_group;");
    }
    asm volatile("cp.async.wait_group 0;" ::: "memory");
    __syncthreads();

    unsigned qfH[8][4], qfL[8][4];
    {
        const int aRow = lane & 15;
        const int aCol = (lane >> 4) * 8;
#pragma unroll
        for (int kc = 0; kc < 8; kc++) {
            LDSM4(qfH[kc],
                  smBase + (ASTG + (warp * 16 + aRow) * ATS + kc * 16 + aCol) * 2);
            LDSM4(qfL[kc],
                  smBase + (ASTG + 2 * ABUF + (warp * 16 + aRow) * ATS + kc * 16 + aCol) * 2);
        }
    }
    __syncthreads();  // Q region may now be overwritten by prefetch

    float oacc[16][4] = {};
    float l0 = 0.f, l1 = 0.f;
    const int gid = lane >> 2, tig = lane & 3;
    const int gr0 = tq * 128 + warp * 16 + gid;

    const int bkRow = ((lane >> 4) & 1) * 8 + (lane & 7);
    const int bkCol = ((lane >> 3) & 1) * 8;
    const int vRow = ((lane >> 3) & 1) * 8 + (lane & 7);
    const int vCol = ((lane >> 4) & 1) * 8;

    const int nTiles = 2 * tq + 2;
    for (int ts = 0; ts < nTiles; ts++) {
        const int stage = ts & 1;
        const unsigned stg = smBase + stage * (ASTG * 2);
        if (ts > 0) {
            asm volatile("cp.async.wait_group 0;" ::: "memory");
            __syncthreads();
        }
        if (ts + 1 < nTiles) {
            const unsigned pst = smBase + (stage ^ 1) * (ASTG * 2);
            size_t kr = kRowBase + (size_t)((ts + 1) * 64 + kvRow) * QKVN + kvCh;
            size_t vr = vRowBase + (size_t)((ts + 1) * 64 + kvRow) * QKVN + kvCh;
#pragma unroll
            for (int c = 0; c < 4; c++) {
                CPA16(pst + (0 * ABUF + kvRow * ATS + kvCh + c * 8) * 2, g_sh + kr + c * 8);
                CPA16(pst + (1 * ABUF + kvRow * ATS + kvCh + c * 8) * 2, g_sl + kr + c * 8);
                CPA16(pst + (2 * ABUF + kvRow * ATS + kvCh + c * 8) * 2, g_sh + vr + c * 8);
                CPA16(pst + (3 * ABUF + kvRow * ATS + kvCh + c * 8) * 2, g_sl + vr + c * 8);
            }
            asm volatile("cp.async.commit_group;");
        }

        // S = softcap(Q K^T) 3-term: each Kh frag feeds Qh AND Ql MMAs;
        // Kl frag feeds Qh only. sa = QhKh + QlKh + QhKl.
        float sa[8][4] = {};
#pragma unroll
        for (int kc = 0; kc < 8; kc++) {
#pragma unroll
            for (int ntp = 0; ntp < 4; ntp++) {
                unsigned bf[4];
                const unsigned boff = ((ntp * 16 + bkRow) * ATS + kc * 16 + bkCol) * 2;
                LDSM4(bf, stg + boff);                // Kh
                MMA_B16(sa[2 * ntp], qfH[kc], bf[0], bf[1]);
                MMA_B16(sa[2 * ntp + 1], qfH[kc], bf[2], bf[3]);
                MMA_B16(sa[2 * ntp], qfL[kc], bf[0], bf[1]);
                MMA_B16(sa[2 * ntp + 1], qfL[kc], bf[2], bf[3]);
                LDSM4(bf, stg + ABUF * 2 + boff);     // Kl
                MMA_B16(sa[2 * ntp], qfH[kc], bf[0], bf[1]);
                MMA_B16(sa[2 * ntp + 1], qfH[kc], bf[2], bf[3]);
            }
        }

        // Clamp-free softcap + causal mask + fixed-max exp:
        // p = exp(-100 / (exp(s/25) + 1)); masked -> 0
        const bool needMask = (ts * 64 + 63) > (tq * 128 + warp * 16);
#pragma unroll
        for (int nt = 0; nt < 8; nt++) {
#pragma unroll
            for (int j = 0; j < 4; j++) {
                float e = __expf(sa[nt][j] * 0.04f);
                float p = __expf(__fdividef(-100.f, e + 1.f));
                if (needMask) {
                    int gc = ts * 64 + nt * 8 + tig * 2 + (j & 1);
                    int gr = gr0 + ((j >= 2) ? 8 : 0);
                    if (gc > gr) p = 0.f;
                }
                sa[nt][j] = p;
                if (j < 2) l0 += p;
                else       l1 += p;
            }
        }

        // Pack P into A fragments (hi + lo)
        unsigned phf[4][4], plf[4][4];
#pragma unroll
        for (int kc = 0; kc < 4; kc++) {
            float c00 = sa[2 * kc][0], c01 = sa[2 * kc][1];
            float c02 = sa[2 * kc][2], c03 = sa[2 * kc][3];
            float c10 = sa[2 * kc + 1][0], c11 = sa[2 * kc + 1][1];
            float c12 = sa[2 * kc + 1][2], c13 = sa[2 * kc + 1][3];
            phf[kc][0] = pack2bf(c00, c01);
            phf[kc][1] = pack2bf(c02, c03);
            phf[kc][2] = pack2bf(c10, c11);
            phf[kc][3] = pack2bf(c12, c13);
#pragma unroll
            for (int r = 0; r < 4; r++) {
                __nv_bfloat162 hv = *(__nv_bfloat162*)&phf[kc][r];
                float2 hf = __bfloat1622float2(hv);
                float a0, a1;
                if (r == 0) { a0 = c00; a1 = c01; }
                else if (r == 1) { a0 = c02; a1 = c03; }
                else if (r == 2) { a0 = c10; a1 = c11; }
                else { a0 = c12; a1 = c13; }
                plf[kc][r] = pack2bf(a0 - hf.x, a1 - hf.y);
            }
        }

        // O += P V 3-term: each Vh frag feeds Ph AND Pl MMAs; Vl feeds Ph.
        // oacc = PhVh + PlVh + PhVl. Byte offsets: Vh @ ABUF*4, Vl @ ABUF*6.
#pragma unroll
        for (int kc = 0; kc < 4; kc++) {
#pragma unroll
            for (int hp = 0; hp < 8; hp++) {
                unsigned bf[4];
                const unsigned voff = ((kc * 16 + vRow) * ATS + hp * 16 + vCol) * 2;
                LDSM4T(bf, stg + ABUF * 4 + voff);    // Vh
                MMA_B16(oacc[2 * hp], phf[kc], bf[0], bf[1]);
                MMA_B16(oacc[2 * hp + 1], phf[kc], bf[2], bf[3]);
                MMA_B16(oacc[2 * hp], plf[kc], bf[0], bf[1]);
                MMA_B16(oacc[2 * hp + 1], plf[kc], bf[2], bf[3]);
                LDSM4T(bf, stg + ABUF * 6 + voff);    // Vl
                MMA_B16(oacc[2 * hp], phf[kc], bf[0], bf[1]);
                MMA_B16(oacc[2 * hp + 1], phf[kc], bf[2], bf[3]);
            }
        }
    }

    // Epilogue: reduce l across the 4-lane row group, normalize, write g_a3
    l0 += __shfl_xor_sync(0xffffffff, l0, 1);
    l0 += __shfl_xor_sync(0xffffffff, l0, 2);
    l1 += __shfl_xor_sync(0xffffffff, l1, 1);
    l1 += __shfl_xor_sync(0xffffffff, l1, 2);
    float inv0 = 1.f / l0, inv1 = 1.f / l1;
    const size_t row0 = (size_t)(b * Tn + tq * 128 + warp * 16 + gid);
#pragma unroll
    for (int nt = 0; nt < 16; nt++) {
        int h = n * HD + nt * 8 + tig * 2;
        float a0 = oacc[nt][0] * inv0, a1 = oacc[nt][1] * inv0;
        float b0v = oacc[nt][2] * inv1, b1v = oacc[nt][3] * inv1;
        unsigned hA = pack2bf(a0, a1);
        unsigned hB = pack2bf(b0v, b1v);
        __nv_bfloat162 hAv = *(__nv_bfloat162*)&hA;
        __nv_bfloat162 hBv = *(__nv_bfloat162*)&hB;
        float2 fA = __bfloat1622float2(hAv);
        float2 fB = __bfloat1622float2(hBv);
        unsigned lA = pack2bf(a0 - fA.x, a1 - fA.y);
        unsigned lB = pack2bf(b0v - fB.x, b1v - fB.y);
        __nv_bfloat16* r0p = g_a3 + row0 * K3 + h;
        __nv_bfloat16* r1p = g_a3 + (row0 + 8) * K3 + h;
        *(unsigned*)r0p = hA;
        *(unsigned*)(r0p + 2048) = hA;
        *(unsigned*)(r0p + 4096) = lA;
        *(unsigned*)r1p = hB;
        *(unsigned*)(r1p + 2048) = hB;
        *(unsigned*)(r1p + 4096) = lB;
    }
}

// ---------------------------------------------------------------------------
extern "C" void kernel_launch(void* const* d_in, const int* in_sizes, int n_in,
                              void* d_out, int out_size) {
    (void)in_sizes; (void)n_in; (void)out_size;
    const float* x = (const float*)d_in[0];
    const int* positions = (const int*)d_in[1];
    const float* w_q = (const float*)d_in[3];
    const float* w_kv = (const float*)d_in[4];
    const float* w_out = (const float*)d_in[5];
    float* out = (float*)d_out;

    const int gemm_smem = NSTG * STG_BY;    // 75776 bytes (>= epi tile 66560)
    cudaFuncSetAttribute(attn_mma_kernel,
                         cudaFuncAttributeMaxDynamicSharedMemorySize, ATTN_SMEM);
    cudaFuncSetAttribute(bf3_gemm_kernel,
                         cudaFuncAttributeMaxDynamicSharedMemorySize, gemm_smem);

    void *p_a3, *p_wb3, *p_wo3;
    cudaGetSymbolAddress(&p_a3, g_a3);
    cudaGetSymbolAddress(&p_wb3, g_wb3);
    cudaGetSymbolAddress(&p_wo3, g_wo3);

    {
        size_t total = (size_t)Dm * QKVN;
        pack_w3_kernel<<<(unsigned)((total + 255) / 256), 256>>>(w_q, w_kv);
    }
    {
        size_t total = (size_t)Dm * ENCN;
        pack_wo3_kernel<<<(unsigned)((total + 255) / 256), 256>>>(w_out);
    }
    {
        size_t total = (size_t)MROWS * 2048;
        split3_kernel<<<(unsigned)((total + 255) / 256), 256>>>(x);
    }
    {
        // QKV projection with fused RoPE + hi/lo split epilogue
        dim3 grid(QKVN / 128, MROWS / 128);
        bf3_gemm_kernel<<<grid, 256, gemm_smem>>>(
            (const __nv_bfloat16*)p_a3, (const __nv_bfloat16*)p_wb3,
            nullptr, QKVN, positions, 1);
    }
    {
        dim3 grid(Tn / 128, NHq, Bsz);
        attn_mma_kernel<<<grid, 256, ATTN_SMEM>>>();
    }
    {
        dim3 grid(ENCN / 128, MROWS / 128);
        bf3_gemm_kernel<<<grid, 256, gemm_smem>>>(
            (const __nv_bfloat16*)p_a3, (const __nv_bfloat16*)p_wo3,
            out, ENCN, nullptr, 0);
    }
}